// round 11
// baseline (speedup 1.0000x reference)
#include <cuda_runtime.h>
#include <cstdint>

// OrderParameter: C=30000 centrals, K=32 neighbors. One warp per central.
// R11: R10 structure + select-chain surgery:
//  - d2 = r - pi/2 shared by both gaussians; tetra center via
//    d1 = d2 - copysign(theta0-pi/2, c)  (squares match theta-space exactly)
//  - gA accumulated unconditionally; true tetra sum g = gA - t1/3 (exact)
//  - single FSETP (gt) per pair
//
//   q_tet   = 1 - 3*S/(n(n-1)),  S via sum c^2 + 2/3 sum c + 31/9 per lane
//   q_tetra = G/(n(n-1))
//   q_oct   = [2*T1 + sum_rows e2s_j*(row_lt_j-1)] / (n*(3+(n-2)(n-3)))
//
// row_lt/e2s packed per row: val = 2.25*e2 + 256 (lt) or 0 (gt); v <= 8006,
// cnt = floor(v/256 + 0.03) exact.

#define FULLMASK 0xffffffffu

__device__ __forceinline__ float ex2f(float x) {
    float r; asm("ex2.approx.f32 %0, %1;" : "=f"(r) : "f"(x)); return r;
}
__device__ __forceinline__ float sqrt_ap(float x) {
    float r; asm("sqrt.approx.f32 %0, %1;" : "=f"(r) : "f"(x)); return r;
}

// ---- constants ----
#define PI_F      3.14159265358979323846f
#define HALF_PI_F 1.57079632679489661923f
#define THETA0_F  1.91061193216957395f     // 109.47 deg
#define DT0_F     0.33981560537467733f     // theta0 - pi/2
#define PMT0_F    1.23098072142021928f     // pi - theta0
#define THR_F     2.79252680319092716f     // 160 deg
#define COS_THR_F (-0.93969262078590838f)  // cos(160 deg)
#define LOG2E_F   1.44269504088896340f
#define D_LT_F    0.17453292519943295f     // 10 deg
#define D1_F      0.20943951023931953f     // 12 deg
#define KG_F  (-LOG2E_F / (2.0f * D_LT_F * D_LT_F))   // 10-deg widths
#define K1_F  (-LOG2E_F / (2.0f * D1_F  * D1_F ))     // term1 (12 deg)

// acos(|c|), A&S 4.4.45 degree-3: |err| <= 6.7e-5 rad on [0,1]
__device__ __forceinline__ float acos_abs(float c) {
    const float t = fabsf(c);
    float p = fmaf(-0.0187293f, t, 0.0742610f);
    p = fmaf(p, t, -0.2121144f);
    p = fmaf(p, t,  1.5707288f);
    return sqrt_ap(__saturatef(1.0f - t)) * p;   // FADD.SAT folds the clamp
}

// One pair's tail in r-space. wsym is a compile-time weight (1.0 or 0.5).
// Accumulates gA (unconditional e1 sum), t1 (gt-only, weight folded),
// returns packed row val (2.25*e2 + 256 for lt, 0 for gt).
__device__ __forceinline__ float pair_tail(float c, float r, float wsym,
                                           float& gA, float& t1)
{
    const bool gt = c < COS_THR_F;                 // theta > 160 deg
    const float d2 = r - HALF_PI_F;                // shared by both gaussians
    // tetra distance: |theta - theta0| == |d2 - copysign(DT0, c)| (lt cases);
    // gt case needs d1 = r (arg = K1*r^2)
    const float csd = copysignf(DT0_F, c);         // LOP3
    const float d1n = d2 - csd;
    const float d1  = gt ? r : d1n;
    const float kk  = gt ? K1_F : KG_F;
    const float e1  = ex2f((kk * d1) * d1);
    gA = fmaf(wsym, e1, gA);                       // unconditional
    t1 = fmaf(gt ? 3.0f * wsym : 0.0f, e1, t1);    // gt-only

    const float e2 = ex2f((KG_F * d2) * d2);
    return gt ? 0.0f : fmaf(2.25f, e2, 256.0f);
}

__global__ __launch_bounds__(256) void order_param_kernel(
    const float* __restrict__ vecs,  // [C, 32, 3]
    const int*   __restrict__ mask,  // [C, 32] int32 0/1
    float* __restrict__ out,         // [3, C]
    int C)
{
    __shared__ float4 sv[8][64];     // per-warp normalized vectors, duplicated

    const int tid  = threadIdx.x;
    const int w    = tid >> 5;
    const int lane = tid & 31;
    const int warp_global = blockIdx.x * 8 + w;
    if (warp_global >= C) return;

    const float* vp = vecs + (size_t)warp_global * 96 + lane * 3;
    const bool valid = mask[(size_t)warp_global * 32 + lane] != 0;
    float x = 0.0f, y = 0.0f, z = 1.0f;
    if (valid) { x = vp[0]; y = vp[1]; z = vp[2]; }
    const float inv = rsqrtf(fmaf(x, x, fmaf(y, y, z * z)));
    x *= inv; y *= inv; z *= inv;

    const unsigned mm = __ballot_sync(FULLMASK, valid);

    float S, G, O;

    if (mm == FULLMASK) {
        // ---------- fast path: all 32 neighbors valid ----------
        const float4 me = make_float4(x, y, z, 0.0f);
        sv[w][lane]      = me;
        sv[w][lane + 32] = me;
        __syncwarp();

        const float4* __restrict__ base = &sv[w][lane];

        float a2 = 0.0f, a1 = 0.0f;          // sum c^2, sum c (unordered, o16 half)
        float gA = 0.0f, t1 = 0.0f;          // unconditional e1 sum; term1 sum
        float vo = 0.0f, vm = 0.0f;          // own/mirror row packed vals

        #pragma unroll
        for (int o = 1; o <= 15; o++) {
            const float4 pv = base[o];       // LDS.128, immediate offset
            const float c = fmaf(x, pv.x, fmaf(y, pv.y, z * pv.z));
            a2 = fmaf(c, c, a2);
            a1 += c;

            const float r = acos_abs(c);
            const float val = pair_tail(c, r, 1.0f, gA, t1);
            vo += val;
            vm += __shfl_sync(FULLMASK, val, lane + (32 - o));  // mirror row
        }
        {   // o = 16: pair computed by both endpoints -> half-weight symmetric,
            // own-only row accumulation (ordered (j, j+16) once)
            const float4 pv = base[16];
            const float c = fmaf(x, pv.x, fmaf(y, pv.y, z * pv.z));
            a2 = fmaf(0.5f * c, c, a2);
            a1 = fmaf(0.5f, c, a1);

            const float r = acos_abs(c);
            const float val = pair_tail(c, r, 0.5f, gA, t1);
            vo += val;
        }

        // per-lane partials; identities hold after the warp reduction
        S = 2.0f * fmaf(2.0f / 3.0f, a1, a2) + 31.0f / 9.0f;
        G = 2.0f * fmaf(-1.0f / 3.0f, t1, gA);          // g = gA - t1/3 (exact)
        const float v   = vo + vm;                      // e2s + 256*row_lt
        const float cnt = floorf(fmaf(v, 1.0f / 256.0f, 0.03f));
        const float e2s = fmaf(-256.0f, cnt, v);
        O = fmaf(e2s, cnt - 1.0f, 2.0f * t1);
    } else {
        // ---------- generic path (verified R3 loop) ----------
        const float NEG_I2DLT2 = -1.0f / (2.0f * D_LT_F * D_LT_F);
        const float NEG_I2D12  = -1.0f / (2.0f * D1_F * D1_F);

        float s_acc = 0.0f, g_acc = 0.0f, t1_acc = 0.0f, e2s = 0.0f;
        int row_lt = 0;
        #pragma unroll
        for (int o = 1; o <= 16; o++) {
            const int p = (lane + o) & 31;
            const float vx = __shfl_sync(FULLMASK, x, p);
            const float vy = __shfl_sync(FULLMASK, y, p);
            const float vz = __shfl_sync(FULLMASK, z, p);
            const bool pv = valid && ((mm >> p) & 1u);
            const float wv = pv ? 1.0f : 0.0f;

            float c = fmaf(x, vx, fmaf(y, vy, z * vz));
            c = fminf(1.0f, fmaxf(-1.0f, c));
            const float th = acosf(c);

            const float a = c + (1.0f / 3.0f);
            const float s_p = wv * a * a;
            const float d0 = th - THETA0_F;
            const float g_p = wv * __expf(d0 * d0 * NEG_I2DLT2);
            const float dpi = th - PI_F;
            const float t1_p = (th > THR_F) ? (3.0f * wv * __expf(dpi * dpi * NEG_I2D12)) : 0.0f;
            const bool lt = pv && (th < THR_F);
            const float dh = th - HALF_PI_F;
            const float e2_p = lt ? (2.25f * __expf(dh * dh * NEG_I2DLT2)) : 0.0f;
            const unsigned ltm = __ballot_sync(FULLMASK, lt);

            if (o < 16) {
                s_acc += s_p; g_acc += g_p; t1_acc += t1_p;
                const int q = (lane - o) & 31;
                e2s += e2_p + __shfl_sync(FULLMASK, e2_p, q);
                row_lt += (int)((ltm >> lane) & 1u) + (int)((ltm >> q) & 1u);
            } else {
                s_acc  = fmaf(0.5f, s_p,  s_acc);
                g_acc  = fmaf(0.5f, g_p,  g_acc);
                t1_acc = fmaf(0.5f, t1_p, t1_acc);
                e2s += e2_p;
                row_lt += (int)((ltm >> lane) & 1u);
            }
        }
        S = 2.0f * s_acc;
        G = 2.0f * g_acc;
        O = fmaf(e2s, (float)(row_lt - 1), 2.0f * t1_acc);
    }

    #pragma unroll
    for (int off = 16; off > 0; off >>= 1) {
        S += __shfl_xor_sync(FULLMASK, S, off);
        G += __shfl_xor_sync(FULLMASK, G, off);
        O += __shfl_xor_sync(FULLMASK, O, off);
    }

    if (lane == 0) {
        const float n   = (float)__popc(mm);
        const float nn1 = n * (n - 1.0f);
        out[warp_global]         = 1.0f - 3.0f * S / nn1;
        out[C + warp_global]     = G / nn1;
        out[2 * C + warp_global] = O / (n * (3.0f + (n - 2.0f) * (n - 3.0f)));
    }
}

extern "C" void kernel_launch(void* const* d_in, const int* in_sizes, int n_in,
                              void* d_out, int out_size) {
    const float* vecs = (const float*)d_in[0];
    const int*   mask = (const int*)d_in[1];
    float* out = (float*)d_out;
    const int C = in_sizes[0] / (32 * 3);

    const int warps_per_block = 8;   // 256 threads
    const int blocks = (C + warps_per_block - 1) / warps_per_block;
    order_param_kernel<<<blocks, 256>>>(vecs, mask, out, C);
}

// round 12
// speedup vs baseline: 1.0808x; 1.0808x over previous
#include <cuda_runtime.h>
#include <cstdint>

// OrderParameter: C=30000 centrals, K=32 neighbors. One warp per central.
// R12: asin-form tail. theta - pi/2 = -asin(c); deg-9 odd Taylor asin (no
// sqrt MUFU, no sign fixups). tetra arg expanded off the e2 arg; term1 via
// the exact series (pi-theta)^2 = 2w + w^2/3, w = 1+c. 2 ex2 per pair total.
//
//   q_tet   = 1 - 3*S/(n(n-1)),  S via sum c^2 + 2/3 sum c + 31/9 per lane
//   q_tetra = G/(n(n-1)),        G = 2*(gA - t1/3) (gA unconditional)
//   q_oct   = [2*T1 + sum_rows e2s_j*(row_lt_j-1)] / (n*(3+(n-2)(n-3)))
//
// row_lt/e2s packed per row: val = 2.25*e2 + 256 (lt) or 0 (gt); v <= 8006,
// cnt = floor(v/256 + 0.03) exact.

#define FULLMASK 0xffffffffu

__device__ __forceinline__ float ex2f(float x) {
    float r; asm("ex2.approx.f32 %0, %1;" : "=f"(r) : "f"(x)); return r;
}
__device__ __forceinline__ float rcpf(float x) {
    float r; asm("rcp.approx.f32 %0, %1;" : "=f"(r) : "f"(x)); return r;
}

// ---- constants ----
#define PI_F      3.14159265358979323846f
#define HALF_PI_F 1.57079632679489661923f
#define THETA0_F  1.91061193216957395f       // 109.47 deg
#define DT0_F     0.33981560537467733f       // theta0 - pi/2
#define THR_F     2.79252680319092716f       // 160 deg
#define COS_THR_F (-0.93969262078590838f)    // cos(160 deg)
#define LOG2E_F   1.44269504088896340f
#define D_LT_F    0.17453292519943295f       // 10 deg
#define D1_F      0.20943951023931953f       // 12 deg
#define KG_F   (-LOG2E_F / (2.0f * D_LT_F * D_LT_F))  // -23.68056
#define K1_F   (-LOG2E_F / (2.0f * D1_F  * D1_F ))    // -16.44483
#define K2DT_F (2.0f * KG_F * DT0_F)                  // -16.09463
#define KDT2_F (KG_F * DT0_F * DT0_F)                 // -2.734670
#define K1_2_F (2.0f * K1_F)                          // -32.88966
#define K1_3_F (K1_F / 3.0f)                          // -5.481610

// One pair's tail. wsym compile-time (1.0 / 0.5). Accumulates gA, t1;
// returns packed row val.
__device__ __forceinline__ float pair_tail(float c, float u, float wsym,
                                           float& gA, float& t1)
{
    // asin(c), deg-9 odd Taylor (accurate where the gaussians are live)
    float p = fmaf(0.030381944f, u, 0.044642857f);
    p = fmaf(p, u, 0.075f);
    p = fmaf(p, u, 0.16666667f);
    const float cu = c * u;
    const float as = fmaf(cu, p, c);          // asin(c);  theta = pi/2 - as

    const float argC = (KG_F * as) * as;                     // KG*(th-pi/2)^2
    const float argB = argC + fmaf(K2DT_F, as, KDT2_F);      // KG*(th-th0)^2
    const bool gt = c < COS_THR_F;                           // theta > 160deg
    const float w1 = 1.0f + c;                               // small for gt
    const float argA = w1 * fmaf(w1, K1_3_F, K1_2_F);        // K1*(th-pi)^2

    const float e1 = ex2f(gt ? argA : argB);
    gA = fmaf(wsym, e1, gA);                        // unconditional
    t1 = fmaf(gt ? 3.0f * wsym : 0.0f, e1, t1);     // term1 (gt only)

    const float e2 = ex2f(argC);
    return gt ? 0.0f : fmaf(2.25f, e2, 256.0f);
}

__global__ __launch_bounds__(256) void order_param_kernel(
    const float* __restrict__ vecs,  // [C, 32, 3]
    const int*   __restrict__ mask,  // [C, 32] int32 0/1
    float* __restrict__ out,         // [3, C]
    int C)
{
    __shared__ float4 sv[8][64];     // per-warp normalized vectors, duplicated

    const int tid  = threadIdx.x;
    const int w    = tid >> 5;
    const int lane = tid & 31;
    const int warp_global = blockIdx.x * 8 + w;
    if (warp_global >= C) return;

    const float* vp = vecs + (size_t)warp_global * 96 + lane * 3;
    const bool valid = mask[(size_t)warp_global * 32 + lane] != 0;
    float x = 0.0f, y = 0.0f, z = 1.0f;
    if (valid) { x = vp[0]; y = vp[1]; z = vp[2]; }
    const float inv = rsqrtf(fmaf(x, x, fmaf(y, y, z * z)));
    x *= inv; y *= inv; z *= inv;

    const unsigned mm = __ballot_sync(FULLMASK, valid);

    float S, G, O;

    if (mm == FULLMASK) {
        // ---------- fast path: all 32 neighbors valid ----------
        const float4 me = make_float4(x, y, z, 0.0f);
        sv[w][lane]      = me;
        sv[w][lane + 32] = me;
        __syncwarp();

        const float4* __restrict__ base = &sv[w][lane];

        float a2 = 0.0f, a1 = 0.0f;          // sum c^2, sum c
        float gA = 0.0f, t1 = 0.0f;          // unconditional e1 sum; term1
        float vo = 0.0f, vm = 0.0f;          // own/mirror row packed vals

        #pragma unroll
        for (int o = 1; o <= 15; o++) {
            const float4 pv = base[o];       // LDS.128, immediate offset
            const float c = fmaf(x, pv.x, fmaf(y, pv.y, z * pv.z));
            const float u = c * c;
            a2 += u;
            a1 += c;

            const float val = pair_tail(c, u, 1.0f, gA, t1);
            vo += val;
            vm += __shfl_sync(FULLMASK, val, lane + (32 - o));  // mirror row
        }
        {   // o = 16: pair computed by both endpoints -> half-weight symmetric,
            // own-only row accumulation (ordered (j, j+16) once)
            const float4 pv = base[16];
            const float c = fmaf(x, pv.x, fmaf(y, pv.y, z * pv.z));
            const float u = c * c;
            a2 = fmaf(0.5f, u, a2);
            a1 = fmaf(0.5f, c, a1);

            const float val = pair_tail(c, u, 0.5f, gA, t1);
            vo += val;
        }

        S = 2.0f * fmaf(2.0f / 3.0f, a1, a2) + 31.0f / 9.0f;
        G = 2.0f * fmaf(-1.0f / 3.0f, t1, gA);          // exact removal of gt e1
        const float v   = vo + vm;                      // e2s + 256*row_lt
        const float cnt = floorf(fmaf(v, 1.0f / 256.0f, 0.03f));
        const float e2s = fmaf(-256.0f, cnt, v);
        O = fmaf(e2s, cnt - 1.0f, 2.0f * t1);
    } else {
        // ---------- generic path (verified R3 loop) ----------
        const float NEG_I2DLT2 = -1.0f / (2.0f * D_LT_F * D_LT_F);
        const float NEG_I2D12  = -1.0f / (2.0f * D1_F * D1_F);

        float s_acc = 0.0f, g_acc = 0.0f, t1_acc = 0.0f, e2s = 0.0f;
        int row_lt = 0;
        #pragma unroll
        for (int o = 1; o <= 16; o++) {
            const int p = (lane + o) & 31;
            const float vx = __shfl_sync(FULLMASK, x, p);
            const float vy = __shfl_sync(FULLMASK, y, p);
            const float vz = __shfl_sync(FULLMASK, z, p);
            const bool pv = valid && ((mm >> p) & 1u);
            const float wv = pv ? 1.0f : 0.0f;

            float c = fmaf(x, vx, fmaf(y, vy, z * vz));
            c = fminf(1.0f, fmaxf(-1.0f, c));
            const float th = acosf(c);

            const float a = c + (1.0f / 3.0f);
            const float s_p = wv * a * a;
            const float d0 = th - THETA0_F;
            const float g_p = wv * __expf(d0 * d0 * NEG_I2DLT2);
            const float dpi = th - PI_F;
            const float t1_p = (th > THR_F) ? (3.0f * wv * __expf(dpi * dpi * NEG_I2D12)) : 0.0f;
            const bool lt = pv && (th < THR_F);
            const float dh = th - HALF_PI_F;
            const float e2_p = lt ? (2.25f * __expf(dh * dh * NEG_I2DLT2)) : 0.0f;
            const unsigned ltm = __ballot_sync(FULLMASK, lt);

            if (o < 16) {
                s_acc += s_p; g_acc += g_p; t1_acc += t1_p;
                const int q = (lane - o) & 31;
                e2s += e2_p + __shfl_sync(FULLMASK, e2_p, q);
                row_lt += (int)((ltm >> lane) & 1u) + (int)((ltm >> q) & 1u);
            } else {
                s_acc  = fmaf(0.5f, s_p,  s_acc);
                g_acc  = fmaf(0.5f, g_p,  g_acc);
                t1_acc = fmaf(0.5f, t1_p, t1_acc);
                e2s += e2_p;
                row_lt += (int)((ltm >> lane) & 1u);
            }
        }
        S = 2.0f * s_acc;
        G = 2.0f * g_acc;
        O = fmaf(e2s, (float)(row_lt - 1), 2.0f * t1_acc);
    }

    #pragma unroll
    for (int off = 16; off > 0; off >>= 1) {
        S += __shfl_xor_sync(FULLMASK, S, off);
        G += __shfl_xor_sync(FULLMASK, G, off);
        O += __shfl_xor_sync(FULLMASK, O, off);
    }

    if (lane == 0) {
        const float n   = (float)__popc(mm);
        const float inv1 = rcpf(n * (n - 1.0f));
        const float inv2 = rcpf(n * (3.0f + (n - 2.0f) * (n - 3.0f)));
        out[warp_global]         = fmaf(-3.0f * S, inv1, 1.0f);
        out[C + warp_global]     = G * inv1;
        out[2 * C + warp_global] = O * inv2;
    }
}

extern "C" void kernel_launch(void* const* d_in, const int* in_sizes, int n_in,
                              void* d_out, int out_size) {
    const float* vecs = (const float*)d_in[0];
    const int*   mask = (const int*)d_in[1];
    float* out = (float*)d_out;
    const int C = in_sizes[0] / (32 * 3);

    const int warps_per_block = 8;   // 256 threads
    const int blocks = (C + warps_per_block - 1) / warps_per_block;
    order_param_kernel<<<blocks, 256>>>(vecs, mask, out, C);
}

// round 13
// speedup vs baseline: 1.0918x; 1.0102x over previous
#include <cuda_runtime.h>
#include <cstdint>

// OrderParameter: C=30000 centrals, K=32 neighbors. One warp per central.
// R13: R12 asin-form math, accumulators split into two independent banks
// (even/odd ring offsets) to break RAW serialization behind the ex2/LDS
// latencies. vo/vm fused (only their sum is used).
//
//   q_tet   = 1 - 3*S/(n(n-1)),  S via sum c^2 + 2/3 sum c + 31/9 per lane
//   q_tetra = G/(n(n-1)),        G = 2*(gA - t1/3) (gA unconditional)
//   q_oct   = [2*T1 + sum_rows e2s_j*(row_lt_j-1)] / (n*(3+(n-2)(n-3)))
//
// row_lt/e2s packed per row: val = 2.25*e2 + 256 (lt) or 0 (gt); v <= 8006,
// cnt = floor(v/256 + 0.03) exact.

#define FULLMASK 0xffffffffu

__device__ __forceinline__ float ex2f(float x) {
    float r; asm("ex2.approx.f32 %0, %1;" : "=f"(r) : "f"(x)); return r;
}
__device__ __forceinline__ float rcpf(float x) {
    float r; asm("rcp.approx.f32 %0, %1;" : "=f"(r) : "f"(x)); return r;
}

// ---- constants ----
#define PI_F      3.14159265358979323846f
#define HALF_PI_F 1.57079632679489661923f
#define THETA0_F  1.91061193216957395f       // 109.47 deg
#define DT0_F     0.33981560537467733f       // theta0 - pi/2
#define THR_F     2.79252680319092716f       // 160 deg
#define COS_THR_F (-0.93969262078590838f)    // cos(160 deg)
#define LOG2E_F   1.44269504088896340f
#define D_LT_F    0.17453292519943295f       // 10 deg
#define D1_F      0.20943951023931953f       // 12 deg
#define KG_F   (-LOG2E_F / (2.0f * D_LT_F * D_LT_F))  // -23.68056
#define K1_F   (-LOG2E_F / (2.0f * D1_F  * D1_F ))    // -16.44483
#define K2DT_F (2.0f * KG_F * DT0_F)                  // -16.09463
#define KDT2_F (KG_F * DT0_F * DT0_F)                 // -2.734670
#define K1_2_F (2.0f * K1_F)                          // -32.88966
#define K1_3_F (K1_F / 3.0f)                          // -5.481610

struct Acc { float a2, a1, gA, t1, v; };

// One pair: dot from LDS-broadcast partner, asin tail, accumulate into bank A.
// wsym compile-time (1.0 or 0.5). mirror: add shfl'd val (false for o=16).
template<int O, bool MIRROR>
__device__ __forceinline__ void pair_step(const float4* __restrict__ base,
                                          float x, float y, float z, int lane,
                                          float wsym, Acc& A)
{
    const float4 pv = base[O];               // LDS.128, immediate offset
    const float c = fmaf(x, pv.x, fmaf(y, pv.y, z * pv.z));
    const float u = c * c;
    A.a2 = fmaf(wsym, u, A.a2);
    A.a1 = fmaf(wsym, c, A.a1);

    // asin(c), deg-9 odd Taylor
    float p = fmaf(0.030381944f, u, 0.044642857f);
    p = fmaf(p, u, 0.075f);
    p = fmaf(p, u, 0.16666667f);
    const float as = fmaf(c * u, p, c);       // theta = pi/2 - as

    const float argC = (KG_F * as) * as;                     // KG*(th-pi/2)^2
    const float argB = argC + fmaf(K2DT_F, as, KDT2_F);      // KG*(th-th0)^2
    const bool gt = c < COS_THR_F;                           // theta > 160deg
    const float w1 = 1.0f + c;
    const float argA = w1 * fmaf(w1, K1_3_F, K1_2_F);        // K1*(th-pi)^2

    const float e1 = ex2f(gt ? argA : argB);
    A.gA = fmaf(wsym, e1, A.gA);
    A.t1 = fmaf(gt ? 3.0f * wsym : 0.0f, e1, A.t1);

    const float e2 = ex2f(argC);
    const float val = gt ? 0.0f : fmaf(2.25f, e2, 256.0f);
    A.v += val;
    if (MIRROR) A.v += __shfl_sync(FULLMASK, val, lane + (32 - O));
}

__global__ __launch_bounds__(256) void order_param_kernel(
    const float* __restrict__ vecs,  // [C, 32, 3]
    const int*   __restrict__ mask,  // [C, 32] int32 0/1
    float* __restrict__ out,         // [3, C]
    int C)
{
    __shared__ float4 sv[8][64];     // per-warp normalized vectors, duplicated

    const int tid  = threadIdx.x;
    const int w    = tid >> 5;
    const int lane = tid & 31;
    const int warp_global = blockIdx.x * 8 + w;
    if (warp_global >= C) return;

    const float* vp = vecs + (size_t)warp_global * 96 + lane * 3;
    const bool valid = mask[(size_t)warp_global * 32 + lane] != 0;
    float x = 0.0f, y = 0.0f, z = 1.0f;
    if (valid) { x = vp[0]; y = vp[1]; z = vp[2]; }
    const float inv = rsqrtf(fmaf(x, x, fmaf(y, y, z * z)));
    x *= inv; y *= inv; z *= inv;

    const unsigned mm = __ballot_sync(FULLMASK, valid);

    float S, G, O;

    if (mm == FULLMASK) {
        // ---------- fast path: all 32 neighbors valid ----------
        const float4 me = make_float4(x, y, z, 0.0f);
        sv[w][lane]      = me;
        sv[w][lane + 32] = me;
        __syncwarp();

        const float4* __restrict__ base = &sv[w][lane];

        Acc A = {0.0f, 0.0f, 0.0f, 0.0f, 0.0f};   // odd offsets
        Acc B = {0.0f, 0.0f, 0.0f, 0.0f, 0.0f};   // even offsets

        pair_step<1,  true>(base, x, y, z, lane, 1.0f, A);
        pair_step<2,  true>(base, x, y, z, lane, 1.0f, B);
        pair_step<3,  true>(base, x, y, z, lane, 1.0f, A);
        pair_step<4,  true>(base, x, y, z, lane, 1.0f, B);
        pair_step<5,  true>(base, x, y, z, lane, 1.0f, A);
        pair_step<6,  true>(base, x, y, z, lane, 1.0f, B);
        pair_step<7,  true>(base, x, y, z, lane, 1.0f, A);
        pair_step<8,  true>(base, x, y, z, lane, 1.0f, B);
        pair_step<9,  true>(base, x, y, z, lane, 1.0f, A);
        pair_step<10, true>(base, x, y, z, lane, 1.0f, B);
        pair_step<11, true>(base, x, y, z, lane, 1.0f, A);
        pair_step<12, true>(base, x, y, z, lane, 1.0f, B);
        pair_step<13, true>(base, x, y, z, lane, 1.0f, A);
        pair_step<14, true>(base, x, y, z, lane, 1.0f, B);
        pair_step<15, true>(base, x, y, z, lane, 1.0f, A);
        // o = 16: both endpoints compute it -> half-weight symmetric sums,
        // own-only row accumulation (ordered (j, j+16) exactly once)
        pair_step<16, false>(base, x, y, z, lane, 0.5f, B);

        const float a2 = A.a2 + B.a2;
        const float a1 = A.a1 + B.a1;
        const float gA = A.gA + B.gA;
        const float t1 = A.t1 + B.t1;
        const float v  = A.v  + B.v;                    // e2s + 256*row_lt

        S = 2.0f * fmaf(2.0f / 3.0f, a1, a2) + 31.0f / 9.0f;
        G = 2.0f * fmaf(-1.0f / 3.0f, t1, gA);          // exact removal of gt e1
        const float cnt = floorf(fmaf(v, 1.0f / 256.0f, 0.03f));
        const float e2s = fmaf(-256.0f, cnt, v);
        O = fmaf(e2s, cnt - 1.0f, 2.0f * t1);
    } else {
        // ---------- generic path (verified R3 loop) ----------
        const float NEG_I2DLT2 = -1.0f / (2.0f * D_LT_F * D_LT_F);
        const float NEG_I2D12  = -1.0f / (2.0f * D1_F * D1_F);

        float s_acc = 0.0f, g_acc = 0.0f, t1_acc = 0.0f, e2s = 0.0f;
        int row_lt = 0;
        #pragma unroll
        for (int o = 1; o <= 16; o++) {
            const int p = (lane + o) & 31;
            const float vx = __shfl_sync(FULLMASK, x, p);
            const float vy = __shfl_sync(FULLMASK, y, p);
            const float vz = __shfl_sync(FULLMASK, z, p);
            const bool pv = valid && ((mm >> p) & 1u);
            const float wv = pv ? 1.0f : 0.0f;

            float c = fmaf(x, vx, fmaf(y, vy, z * vz));
            c = fminf(1.0f, fmaxf(-1.0f, c));
            const float th = acosf(c);

            const float a = c + (1.0f / 3.0f);
            const float s_p = wv * a * a;
            const float d0 = th - THETA0_F;
            const float g_p = wv * __expf(d0 * d0 * NEG_I2DLT2);
            const float dpi = th - PI_F;
            const float t1_p = (th > THR_F) ? (3.0f * wv * __expf(dpi * dpi * NEG_I2D12)) : 0.0f;
            const bool lt = pv && (th < THR_F);
            const float dh = th - HALF_PI_F;
            const float e2_p = lt ? (2.25f * __expf(dh * dh * NEG_I2DLT2)) : 0.0f;
            const unsigned ltm = __ballot_sync(FULLMASK, lt);

            if (o < 16) {
                s_acc += s_p; g_acc += g_p; t1_acc += t1_p;
                const int q = (lane - o) & 31;
                e2s += e2_p + __shfl_sync(FULLMASK, e2_p, q);
                row_lt += (int)((ltm >> lane) & 1u) + (int)((ltm >> q) & 1u);
            } else {
                s_acc  = fmaf(0.5f, s_p,  s_acc);
                g_acc  = fmaf(0.5f, g_p,  g_acc);
                t1_acc = fmaf(0.5f, t1_p, t1_acc);
                e2s += e2_p;
                row_lt += (int)((ltm >> lane) & 1u);
            }
        }
        S = 2.0f * s_acc;
        G = 2.0f * g_acc;
        O = fmaf(e2s, (float)(row_lt - 1), 2.0f * t1_acc);
    }

    #pragma unroll
    for (int off = 16; off > 0; off >>= 1) {
        S += __shfl_xor_sync(FULLMASK, S, off);
        G += __shfl_xor_sync(FULLMASK, G, off);
        O += __shfl_xor_sync(FULLMASK, O, off);
    }

    if (lane == 0) {
        const float n   = (float)__popc(mm);
        const float inv1 = rcpf(n * (n - 1.0f));
        const float inv2 = rcpf(n * (3.0f + (n - 2.0f) * (n - 3.0f)));
        out[warp_global]         = fmaf(-3.0f * S, inv1, 1.0f);
        out[C + warp_global]     = G * inv1;
        out[2 * C + warp_global] = O * inv2;
    }
}

extern "C" void kernel_launch(void* const* d_in, const int* in_sizes, int n_in,
                              void* d_out, int out_size) {
    const float* vecs = (const float*)d_in[0];
    const int*   mask = (const int*)d_in[1];
    float* out = (float*)d_out;
    const int C = in_sizes[0] / (32 * 3);

    const int warps_per_block = 8;   // 256 threads
    const int blocks = (C + warps_per_block - 1) / warps_per_block;
    order_param_kernel<<<blocks, 256>>>(vecs, mask, out, C);
}